// round 13
// baseline (speedup 1.0000x reference)
#include <cuda_runtime.h>
#include <math_constants.h>

// Problem dims (fixed instance)
#define BQ  4
#define FQ  256
#define TQ  60000
#define NBQ 8
#define FB  32
#define ND  5
#define NLA 11
#define NG  15
#define EPSQ 1e-8f
#define LN2F 0.6931471805599453f

// K1 geometry: block = 128 thr (4 warps) on one 512-t span;
// warps split the 32 freq rows 8 each; lane owns 16 consecutive t.
#define ELPL   16
#define K1W    4
#define K1B    (K1W * 32)        // 128
#define K1SPAN (ELPL * 32)       // 512
#define ROWS_PER_WARP (FB / K1W) // 8

#define TT2K 512   // k2 tile
#define H3   19    // halo: 5 (moving-avg) + 7 (gauss) + 7 (fuse gauss)
#define NTILE ((TQ + TT2K - 1) / TT2K)   // 118

// ---- scratch (static device arrays; no allocation) ----
__device__ float g_xp[BQ * NBQ * TQ];   // pooled band envelopes  [B, NB, T]
__device__ float g_xg[BQ * TQ];         // smoothed flux (pre-norm)
__device__ float g_C[BQ * TQ];          // conv15(xg, fg_w), zero-padded
__device__ int   g_maxxg_bits[BQ];      // xg >= 0 -> plain int max works
__device__ int   g_maxC_key[BQ];        // monotone float->int keys
__device__ int   g_minC_key[BQ];

// monotone involution float <-> signed-int key (total order incl. negatives)
__device__ __forceinline__ int f2key(float v) {
    int u = __float_as_int(v);
    return (u >= 0) ? u : (u ^ 0x7FFFFFFF);
}
__device__ __forceinline__ float key2f(int k) {
    int u = (k >= 0) ? k : (k ^ 0x7FFFFFFF);
    return __int_as_float(u);
}

// ============================================================================
// K1: x[b] -> xp[b]   (per-batch launch; body frozen from R8/R12)
//   No gridsync: depends only on kernel inputs; disjoint per-batch output.
// ============================================================================
__global__ __launch_bounds__(K1B, 10) void k1_xp(
    const float* __restrict__ x,
    const float* __restrict__ log_gamma,
    const float* __restrict__ diff_w,
    const float* __restrict__ diff_b,
    const int b)
{
    __shared__ float sred[K1W][K1SPAN];

    const int tid = threadIdx.x;
    // init this batch's scalars (k2_b gridsyncs on this kernel)
    if (blockIdx.x == 0 && blockIdx.y == 0 && tid == 0) {
        g_maxxg_bits[b] = 0;                     // xg >= 0
        g_maxC_key[b]   = (int)0x80000000;       // -> -inf
        g_minC_key[b]   = 0x7FFFFFFF;            // -> +inf
    }

    const int warp = tid >> 5;
    const int lane = tid & 31;
    const int band = blockIdx.y;
    const int t0   = blockIdx.x * K1SPAN;
    const int tbase = t0 + ELPL * lane;
    const bool inr  = (tbase < TQ);       // TQ % 16 == 0 -> all 16 in range

    const float gamma = __expf(log_gamma[band]);
    // ln2 folded into the diff taps: conv(ln y) = sum (dw*ln2) * log2(y)
    const float dw0 = diff_w[band * ND + 0] * LN2F;
    const float dw1 = diff_w[band * ND + 1] * LN2F;
    const float dw2 = diff_w[band * ND + 2] * LN2F;
    const float dw3 = diff_w[band * ND + 3] * LN2F;
    const float dw4 = diff_w[band * ND + 4] * LN2F;
    const float db  = diff_b[band];

    // per-lane row pointer (bumped by TQ per row); halo pointer alongside
    const float* p = x + ((size_t)b * FQ + (size_t)band * FB
                          + (size_t)warp * ROWS_PER_WARP) * TQ + tbase;
    const bool  em  = (lane == 0);
    const float* ph = p + (em ? -2 : ELPL);
    // loop-invariant halo validity (tbase is a multiple of 16)
    const bool h0ok = (em && tbase >= 2) ||
                      (lane == 31 && inr && (tbase + ELPL     < TQ));
    const bool h1ok = (em && tbase >= 2) ||
                      (lane == 31 && inr && (tbase + ELPL + 1 < TQ));

    float acc[ELPL];
#pragma unroll
    for (int j = 0; j < ELPL; ++j) acc[j] = 0.f;

#pragma unroll 1
    for (int f = 0; f < ROWS_PER_WARP; ++f) {
        float4 v0 = {0.f,0.f,0.f,0.f}, v1 = v0, v2 = v0, v3 = v0;
        if (inr) v0 = __ldcs((const float4*)(p));
        if (inr) v1 = __ldcs((const float4*)(p + 4));
        if (inr) v2 = __ldcs((const float4*)(p + 8));
        if (inr) v3 = __ldcs((const float4*)(p + 12));
        float rv0 = 0.f, rv1 = 0.f;
        if (h0ok) rv0 = __ldcs(ph);
        if (h1ok) rv1 = __ldcs(ph + 1);

        float e[ELPL + 4];   // log2 window, t in [tbase-2, tbase+ELPL+2)
        e[2]  = __log2f(fmaf(gamma, v0.x, 1.0f));
        e[3]  = __log2f(fmaf(gamma, v0.y, 1.0f));
        e[4]  = __log2f(fmaf(gamma, v0.z, 1.0f));
        e[5]  = __log2f(fmaf(gamma, v0.w, 1.0f));
        e[6]  = __log2f(fmaf(gamma, v1.x, 1.0f));
        e[7]  = __log2f(fmaf(gamma, v1.y, 1.0f));
        e[8]  = __log2f(fmaf(gamma, v1.z, 1.0f));
        e[9]  = __log2f(fmaf(gamma, v1.w, 1.0f));
        e[10] = __log2f(fmaf(gamma, v2.x, 1.0f));
        e[11] = __log2f(fmaf(gamma, v2.y, 1.0f));
        e[12] = __log2f(fmaf(gamma, v2.z, 1.0f));
        e[13] = __log2f(fmaf(gamma, v2.w, 1.0f));
        e[14] = __log2f(fmaf(gamma, v3.x, 1.0f));
        e[15] = __log2f(fmaf(gamma, v3.y, 1.0f));
        e[16] = __log2f(fmaf(gamma, v3.z, 1.0f));
        e[17] = __log2f(fmaf(gamma, v3.w, 1.0f));

        // halo via shuffles; OOB neighbors carry 0 == zero padding
        e[0]        = __shfl_up_sync(0xffffffffu, e[ELPL], 1);
        e[1]        = __shfl_up_sync(0xffffffffu, e[ELPL + 1], 1);
        e[ELPL + 2] = __shfl_down_sync(0xffffffffu, e[2], 1);
        e[ELPL + 3] = __shfl_down_sync(0xffffffffu, e[3], 1);
        // edge fixup, branch-free: invalid rv=0 -> log2(fma(g,0,1)) = 0
        float h0 = __log2f(fmaf(gamma, rv0, 1.0f));
        float h1 = __log2f(fmaf(gamma, rv1, 1.0f));
        e[0]        = em ? h0 : e[0];
        e[1]        = em ? h1 : e[1];
        e[ELPL + 2] = (lane == 31) ? h0 : e[ELPL + 2];
        e[ELPL + 3] = (lane == 31) ? h1 : e[ELPL + 3];

#pragma unroll
        for (int j = 0; j < ELPL; ++j) {
            float s = db;
            s = fmaf(dw0, e[j],     s);
            s = fmaf(dw1, e[j + 1], s);
            s = fmaf(dw2, e[j + 2], s);
            s = fmaf(dw3, e[j + 3], s);
            s = fmaf(dw4, e[j + 4], s);
            acc[j] += fmaxf(s, 0.f);
        }

        p  += TQ;
        ph += TQ;
    }

    // combine the 4 warps' partial sums through smem
#pragma unroll
    for (int q = 0; q < 4; ++q)
        *(float4*)&sred[warp][ELPL * lane + 4 * q] =
            make_float4(acc[4*q], acc[4*q+1], acc[4*q+2], acc[4*q+3]);
    __syncthreads();

    {
        int i0 = 4 * tid;                      // 0..508
        int t  = t0 + i0;
        if (t < TQ) {                          // TQ%4==0 -> whole float4 in range
            float4 r0 = *(const float4*)&sred[0][i0];
            float4 r1 = *(const float4*)&sred[1][i0];
            float4 r2 = *(const float4*)&sred[2][i0];
            float4 r3 = *(const float4*)&sred[3][i0];
            float4 o;
            o.x = (r0.x + r1.x) + (r2.x + r3.x);
            o.y = (r0.y + r1.y) + (r2.y + r3.y);
            o.z = (r0.z + r1.z) + (r2.z + r3.z);
            o.w = (r0.w + r1.w) + (r2.w + r3.w);
            *(float4*)&g_xp[((size_t)b * NBQ + band) * TQ + t] = o;
        }
    }
    cudaTriggerProgrammaticLaunchCompletion();
}

// ============================================================================
// K2 (per-batch): xp[b] -> xg[b], C[b], per-batch scalar atomics.
//   Triggers at entry so k3_b and the NEXT batch's k1 launch immediately;
//   gridsync gates the actual data use on k1_b completion.
// ============================================================================
__global__ __launch_bounds__(256) void k2_xgC(
    const float* __restrict__ la_w, const float* __restrict__ la_b,
    const float* __restrict__ mix_w,
    const float* __restrict__ g_w,  const float* __restrict__ g_b,
    const float* __restrict__ fg_w,
    const int b)
{
    __shared__ __align__(16) float sxp[NBQ][552];  // 550 valid + pad
    __shared__ __align__(16) float sxm[544];       // 540 valid + pad
    __shared__ __align__(16) float sxg[528];       // 526 valid + pad
    __shared__ float wlaw[NBQ * NLA], wg[NG], wfg[NG], wlab[NBQ], wmw[NBQ];

    cudaTriggerProgrammaticLaunchCompletion();   // let successors launch early

    const int t0  = blockIdx.x * TT2K;
    const int tid = threadIdx.x;

    // prologue: kernel inputs only (safe before the PDL dependency point)
    if (tid < NBQ * NLA) wlaw[tid] = la_w[tid];
    if (tid < NG)        { wg[tid] = g_w[tid]; wfg[tid] = fg_w[tid]; }
    if (tid < NBQ)       { wlab[tid] = la_b[tid]; wmw[tid] = mix_w[tid]; }
    const float gb = g_b[0];

    cudaGridDependencySynchronize();   // wait for k1_b's g_xp / scalar init

    for (int n = tid; n < NBQ * 550; n += 256) {
        int band = n / 550;
        int i    = n - band * 550;
        int t    = t0 - H3 + i;
        sxp[band][i] = (t >= 0 && t < TQ)
                     ? g_xp[((size_t)b * NBQ + band) * TQ + t] : 0.0f;
    }
    __syncthreads();

    // xm groups: thread t<135 computes xm[4t .. 4t+3] (t of xm[i] = t0-14+i)
    if (tid < 135) {
        const int i0 = 4 * tid;
        float xm0 = 0.f, xm1 = 0.f, xm2 = 0.f, xm3 = 0.f;
#pragma unroll
        for (int band = 0; band < NBQ; ++band) {
            float4 a0 = *(const float4*)&sxp[band][i0];
            float4 a1 = *(const float4*)&sxp[band][i0 + 4];
            float4 a2 = *(const float4*)&sxp[band][i0 + 8];
            float4 a3 = *(const float4*)&sxp[band][i0 + 12];
            float w[16] = {a0.x,a0.y,a0.z,a0.w, a1.x,a1.y,a1.z,a1.w,
                           a2.x,a2.y,a2.z,a2.w, a3.x,a3.y,a3.z,a3.w};
            const float lb = wlab[band], mw = wmw[band];
            float c0 = lb, c1 = lb, c2 = lb, c3 = lb;
#pragma unroll
            for (int j = 0; j < NLA; ++j) {
                float lw = wlaw[band * NLA + j];
                c0 = fmaf(lw, w[j],     c0);
                c1 = fmaf(lw, w[j + 1], c1);
                c2 = fmaf(lw, w[j + 2], c2);
                c3 = fmaf(lw, w[j + 3], c3);
            }
            xm0 = fmaf(mw, w[5] - c0, xm0);
            xm1 = fmaf(mw, w[6] - c1, xm1);
            xm2 = fmaf(mw, w[7] - c2, xm2);
            xm3 = fmaf(mw, w[8] - c3, xm3);
        }
        const int tb = t0 - 14 + i0;
        if (tb + 0 < 0 || tb + 0 >= TQ) xm0 = 0.f;
        if (tb + 1 < 0 || tb + 1 >= TQ) xm1 = 0.f;
        if (tb + 2 < 0 || tb + 2 >= TQ) xm2 = 0.f;
        if (tb + 3 < 0 || tb + 3 >= TQ) xm3 = 0.f;
        *(float4*)&sxm[i0] = make_float4(xm0, xm1, xm2, xm3);
    }
    __syncthreads();

    // xg groups: thread t<132 computes xg[4t .. 4t+3] (t of xg[j] = t0-7+j)
    if (tid < 132) {
        const int j0 = 4 * tid;
        float4 a0 = *(const float4*)&sxm[j0];
        float4 a1 = *(const float4*)&sxm[j0 + 4];
        float4 a2 = *(const float4*)&sxm[j0 + 8];
        float4 a3 = *(const float4*)&sxm[j0 + 12];
        float4 a4 = *(const float4*)&sxm[j0 + 16];
        float w[20] = {a0.x,a0.y,a0.z,a0.w, a1.x,a1.y,a1.z,a1.w,
                       a2.x,a2.y,a2.z,a2.w, a3.x,a3.y,a3.z,a3.w,
                       a4.x,a4.y,a4.z,a4.w};
        float s0 = gb, s1 = gb, s2 = gb, s3 = gb;
#pragma unroll
        for (int k = 0; k < NG; ++k) {
            float g = wg[k];
            s0 = fmaf(g, w[k],     s0);
            s1 = fmaf(g, w[k + 1], s1);
            s2 = fmaf(g, w[k + 2], s2);
            s3 = fmaf(g, w[k + 3], s3);
        }
        const int tb = t0 - 7 + j0;
        float x0 = (tb + 0 >= 0 && tb + 0 < TQ && j0 + 0 < 526) ? fmaxf(s0, 0.f) : 0.f;
        float x1 = (tb + 1 >= 0 && tb + 1 < TQ && j0 + 1 < 526) ? fmaxf(s1, 0.f) : 0.f;
        float x2 = (tb + 2 >= 0 && tb + 2 < TQ && j0 + 2 < 526) ? fmaxf(s2, 0.f) : 0.f;
        float x3 = (tb + 3 >= 0 && tb + 3 < TQ && j0 + 3 < 526) ? fmaxf(s3, 0.f) : 0.f;
        *(float4*)&sxg[j0] = make_float4(x0, x1, x2, x3);
    }
    __syncthreads();

    // C + emit phase: thread t<128 handles t = t0+4t .. +3 (group fully
    // valid or fully invalid since TQ % 4 == 0).
    float lmaxg = 0.0f;
    float lmaxC = -CUDART_INF_F, lminC = CUDART_INF_F;
    if (tid < 128) {
        const int i0 = 4 * tid;
        const int t  = t0 + i0;
        if (t < TQ) {
            float4 a0 = *(const float4*)&sxg[i0];
            float4 a1 = *(const float4*)&sxg[i0 + 4];
            float4 a2 = *(const float4*)&sxg[i0 + 8];
            float4 a3 = *(const float4*)&sxg[i0 + 12];
            float4 a4 = *(const float4*)&sxg[i0 + 16];
            float w[20] = {a0.x,a0.y,a0.z,a0.w, a1.x,a1.y,a1.z,a1.w,
                           a2.x,a2.y,a2.z,a2.w, a3.x,a3.y,a3.z,a3.w,
                           a4.x,a4.y,a4.z,a4.w};
            float C0 = 0.f, C1 = 0.f, C2 = 0.f, C3 = 0.f;
#pragma unroll
            for (int k = 0; k < NG; ++k) {
                float f = wfg[k];
                C0 = fmaf(f, w[k],     C0);
                C1 = fmaf(f, w[k + 1], C1);
                C2 = fmaf(f, w[k + 2], C2);
                C3 = fmaf(f, w[k + 3], C3);
            }
            size_t n4 = ((size_t)b * TQ + t) / 4;
            ((float4*)g_xg)[n4] = make_float4(w[7], w[8], w[9], w[10]);
            ((float4*)g_C)[n4]  = make_float4(C0, C1, C2, C3);
            lmaxg = fmaxf(fmaxf(w[7], w[8]), fmaxf(w[9], w[10]));
            // interior max/min of C (t in [7, TQ-7))
            if (t + 0 >= 7 && t + 0 < TQ - 7) { lmaxC = fmaxf(lmaxC, C0); lminC = fminf(lminC, C0); }
            if (t + 1 >= 7 && t + 1 < TQ - 7) { lmaxC = fmaxf(lmaxC, C1); lminC = fminf(lminC, C1); }
            if (t + 2 >= 7 && t + 2 < TQ - 7) { lmaxC = fmaxf(lmaxC, C2); lminC = fminf(lminC, C2); }
            if (t + 3 >= 7 && t + 3 < TQ - 7) { lmaxC = fmaxf(lmaxC, C3); lminC = fminf(lminC, C3); }
        }
    }
    int kmax = f2key(lmaxC), kmin = f2key(lminC);
#pragma unroll
    for (int off = 16; off; off >>= 1) {
        lmaxg = fmaxf(lmaxg, __shfl_xor_sync(0xffffffffu, lmaxg, off));
        kmax  = max(kmax, __shfl_xor_sync(0xffffffffu, kmax, off));
        kmin  = min(kmin, __shfl_xor_sync(0xffffffffu, kmin, off));
    }
    if ((tid & 31) == 0) {
        atomicMax(&g_maxxg_bits[b], __float_as_int(lmaxg));  // xg >= 0
        atomicMax(&g_maxC_key[b], kmax);
        atomicMin(&g_minC_key[b], kmin);
    }
}

// ============================================================================
// K3 (per-batch): elementwise finale, float4-wide. Triggers at entry so the
// next batch's k1 launches immediately (no data dependency on this kernel).
// ============================================================================
__global__ __launch_bounds__(128) void k3_out(
    const float* __restrict__ fc_w, const float* __restrict__ fc_b,
    const float* __restrict__ fg_w, const float* __restrict__ fg_b,
    float* __restrict__ out_sf, float* __restrict__ out_fn,
    const int b)
{
    __shared__ float swfg[NG];
    __shared__ float sc[6];   // inv, a, dn, d_interior, cb, fgb

    cudaTriggerProgrammaticLaunchCompletion();   // next batch's k1 may start

    const int tid = threadIdx.x;
    const int t4  = blockIdx.x * 128 + tid;   // float4 index
    const int t   = 4 * t4;

    if (tid < NG) swfg[tid] = fg_w[tid];      // input-only prologue

    cudaGridDependencySynchronize();          // wait for k2_b's xg/C/scalars
    __syncthreads();

    if (tid == 0) {
        const float cb  = fc_b[0];
        const float fgb = fg_b[0];
        float S = fc_w[0] + fc_w[1] + fc_w[2] + fc_w[3];
        float maxxg = __int_as_float(g_maxxg_bits[b]);
        float inv = 1.0f / (maxxg + EPSQ);
        float a   = S * inv;
        float Wfull = 0.0f;
#pragma unroll
        for (int k = 0; k < NG; ++k) Wfull += swfg[k];
        float d_int = fmaf(cb, Wfull, fgb);
        float maxC = key2f(g_maxC_key[b]);
        float minC = key2f(g_minC_key[b]);
        float best = fmaf(a, (a >= 0.0f) ? maxC : minC, d_int);
        // 14 edge positions: t in [0,7) U [T-7, T)
#pragma unroll
        for (int e = 0; e < 14; ++e) {
            int tt = (e < 7) ? e : (TQ - 14 + e);
            float Wt = 0.0f;
#pragma unroll
            for (int k = 0; k < NG; ++k) {
                int p = tt - 7 + k;
                if (p >= 0 && p < TQ) Wt += swfg[k];
            }
            float fsv = fmaf(a, g_C[(size_t)b * TQ + tt], fmaf(cb, Wt, fgb));
            best = fmaxf(best, fsv);
        }
        float famax = 1.0f / (1.0f + __expf(-best));
        sc[0] = inv;
        sc[1] = a;
        sc[2] = 1.0f / (famax + EPSQ);
        sc[3] = d_int;
        sc[4] = cb;
        sc[5] = fgb;
    }
    __syncthreads();

    if (t < TQ) {   // TQ % 4 == 0 -> full float4 in range
        size_t n4 = (size_t)b * (TQ / 4) + t4;
        float4 xg4 = ((const float4*)g_xg)[n4];
        float4 C4  = ((const float4*)g_C)[n4];
        const float inv = sc[0], a = sc[1], dn = sc[2], d_int = sc[3];

        float4 sf4;
        sf4.x = xg4.x * inv; sf4.y = xg4.y * inv;
        sf4.z = xg4.z * inv; sf4.w = xg4.w * inv;
        ((float4*)out_sf)[n4] = sf4;

        float d0 = d_int, d1 = d_int, d2 = d_int, d3 = d_int;
        if (t < 7 || t + 3 >= TQ - 7) {   // rare edge slow path
            const float cb = sc[4], fgb = sc[5];
#pragma unroll
            for (int q = 0; q < 4; ++q) {
                int tt = t + q;
                float Wt = 0.0f;
#pragma unroll
                for (int k = 0; k < NG; ++k) {
                    int p = tt - 7 + k;
                    if (p >= 0 && p < TQ) Wt += swfg[k];
                }
                float dv = fmaf(cb, Wt, fgb);
                if (q == 0) d0 = dv; else if (q == 1) d1 = dv;
                else if (q == 2) d2 = dv; else d3 = dv;
            }
        }
        float4 o;
        o.x = dn / (1.0f + __expf(-fmaf(a, C4.x, d0)));
        o.y = dn / (1.0f + __expf(-fmaf(a, C4.y, d1)));
        o.z = dn / (1.0f + __expf(-fmaf(a, C4.z, d2)));
        o.w = dn / (1.0f + __expf(-fmaf(a, C4.w, d3)));
        ((float4*)out_fn)[n4] = o;
    }
}

// ============================================================================
extern "C" void kernel_launch(void* const* d_in, const int* in_sizes, int n_in,
                              void* d_out, int out_size)
{
    const float* x         = (const float*)d_in[0];
    const float* log_gamma = (const float*)d_in[1];
    const float* diff_w    = (const float*)d_in[2];
    const float* diff_b    = (const float*)d_in[3];
    const float* la_w      = (const float*)d_in[4];
    const float* la_b      = (const float*)d_in[5];
    const float* mix_w     = (const float*)d_in[6];
    const float* g_w       = (const float*)d_in[7];
    const float* g_b       = (const float*)d_in[8];
    const float* fc_w      = (const float*)d_in[9];
    const float* fc_b      = (const float*)d_in[10];
    const float* fg_w      = (const float*)d_in[11];
    const float* fg_b      = (const float*)d_in[12];
    float* out = (float*)d_out;

    cudaLaunchAttribute attr[1];
    attr[0].id = cudaLaunchAttributeProgrammaticStreamSerialization;
    attr[0].val.programmaticStreamSerializationAllowed = 1;

    for (int b = 0; b < BQ; ++b) {
        {   // k1_b: no gridsync inside (independent of predecessor k3_{b-1})
            cudaLaunchConfig_t cfg = {};
            cfg.gridDim  = dim3((TQ + K1SPAN - 1) / K1SPAN, NBQ, 1); // 118x8
            cfg.blockDim = dim3(K1B, 1, 1);
            cfg.stream   = (cudaStream_t)0;
            // PDL attr on b>0 lets k1_b start while batch b-1's tail runs;
            // b==0 launches normally (clean start of each graph replay).
            cfg.attrs    = attr;
            cfg.numAttrs = (b > 0) ? 1 : 0;
            cudaLaunchKernelEx(&cfg, k1_xp, x, log_gamma, diff_w, diff_b, b);
        }
        {   // k2_b: gridsync on k1_b (immediate predecessor)
            cudaLaunchConfig_t cfg = {};
            cfg.gridDim  = dim3(NTILE, 1, 1);                        // 118
            cfg.blockDim = dim3(256, 1, 1);
            cfg.stream   = (cudaStream_t)0;
            cfg.attrs    = attr;
            cfg.numAttrs = 1;
            cudaLaunchKernelEx(&cfg, k2_xgC, la_w, la_b, mix_w, g_w, g_b,
                               fg_w, b);
        }
        {   // k3_b: gridsync on k2_b (immediate predecessor)
            cudaLaunchConfig_t cfg = {};
            cfg.gridDim  = dim3((TQ / 4 + 127) / 128, 1, 1);         // 118
            cfg.blockDim = dim3(128, 1, 1);
            cfg.stream   = (cudaStream_t)0;
            cfg.attrs    = attr;
            cfg.numAttrs = 1;
            cudaLaunchKernelEx(&cfg, k3_out, fc_w, fc_b, fg_w, fg_b,
                               out, out + (size_t)BQ * TQ, b);
        }
    }
}

// round 14
// speedup vs baseline: 1.2732x; 1.2732x over previous
#include <cuda_runtime.h>
#include <math_constants.h>

// Problem dims (fixed instance)
#define BQ  4
#define FQ  256
#define TQ  60000
#define NBQ 8
#define FB  32
#define ND  5
#define NLA 11
#define NG  15
#define EPSQ 1e-8f
#define LN2F 0.6931471805599453f

// K1 geometry: block = 128 thr (4 warps) on one 512-t span;
// warps split the 32 freq rows 8 each; lane owns 16 consecutive t.
#define ELPL   16
#define K1W    4
#define K1B    (K1W * 32)        // 128
#define K1SPAN (ELPL * 32)       // 512
#define ROWS_PER_WARP (FB / K1W) // 8

#define TT2K 512   // k2 tile
#define H3   19    // halo: 5 (moving-avg) + 7 (gauss) + 7 (fuse gauss)
#define NTILE ((TQ + TT2K - 1) / TT2K)   // 118

// ---- scratch (static device arrays; no allocation) ----
__device__ float g_xp[BQ * NBQ * TQ];   // pooled band envelopes  [B, NB, T]
__device__ float g_xg[BQ * TQ];         // smoothed flux (pre-norm)
__device__ float g_C[BQ * TQ];          // conv15(xg, fg_w), zero-padded
__device__ int   g_maxxg_bits[BQ];      // xg >= 0 -> plain int max works
__device__ int   g_maxC_key[BQ];        // monotone float->int keys
__device__ int   g_minC_key[BQ];

// monotone involution float <-> signed-int key (total order incl. negatives)
__device__ __forceinline__ int f2key(float v) {
    int u = __float_as_int(v);
    return (u >= 0) ? u : (u ^ 0x7FFFFFFF);
}
__device__ __forceinline__ float key2f(int k) {
    int u = (k >= 0) ? k : (k ^ 0x7FFFFFFF);
    return __int_as_float(u);
}

// ============================================================================
// K1: x [B,F,T] -> xp [B,NB,T]   (FROZEN — R8/R12-identical + PDL trigger)
// ============================================================================
__global__ __launch_bounds__(K1B, 10) void k1_xp(
    const float* __restrict__ x,
    const float* __restrict__ log_gamma,
    const float* __restrict__ diff_w,
    const float* __restrict__ diff_b)
{
    __shared__ float sred[K1W][K1SPAN];

    const int tid = threadIdx.x;
    // fold scalar init here (tail reads these only after k1 completes)
    if (blockIdx.x == 0 && blockIdx.y == 0 && blockIdx.z == 0 && tid < BQ) {
        g_maxxg_bits[tid] = 0;                     // xg >= 0
        g_maxC_key[tid]   = (int)0x80000000;       // -> -inf
        g_minC_key[tid]   = 0x7FFFFFFF;            // -> +inf
    }

    const int warp = tid >> 5;
    const int lane = tid & 31;
    const int band = blockIdx.y;
    const int b    = blockIdx.z;
    const int t0   = blockIdx.x * K1SPAN;
    const int tbase = t0 + ELPL * lane;
    const bool inr  = (tbase < TQ);       // TQ % 16 == 0 -> all 16 in range

    const float gamma = __expf(log_gamma[band]);
    // ln2 folded into the diff taps: conv(ln y) = sum (dw*ln2) * log2(y)
    const float dw0 = diff_w[band * ND + 0] * LN2F;
    const float dw1 = diff_w[band * ND + 1] * LN2F;
    const float dw2 = diff_w[band * ND + 2] * LN2F;
    const float dw3 = diff_w[band * ND + 3] * LN2F;
    const float dw4 = diff_w[band * ND + 4] * LN2F;
    const float db  = diff_b[band];

    // per-lane row pointer (bumped by TQ per row); halo pointer alongside
    const float* p = x + ((size_t)b * FQ + (size_t)band * FB
                          + (size_t)warp * ROWS_PER_WARP) * TQ + tbase;
    const bool  em  = (lane == 0);
    const float* ph = p + (em ? -2 : ELPL);
    // loop-invariant halo validity (tbase is a multiple of 16)
    const bool h0ok = (em && tbase >= 2) ||
                      (lane == 31 && inr && (tbase + ELPL     < TQ));
    const bool h1ok = (em && tbase >= 2) ||
                      (lane == 31 && inr && (tbase + ELPL + 1 < TQ));

    float acc[ELPL];
#pragma unroll
    for (int j = 0; j < ELPL; ++j) acc[j] = 0.f;

#pragma unroll 1
    for (int f = 0; f < ROWS_PER_WARP; ++f) {
        float4 v0 = {0.f,0.f,0.f,0.f}, v1 = v0, v2 = v0, v3 = v0;
        if (inr) v0 = __ldcs((const float4*)(p));
        if (inr) v1 = __ldcs((const float4*)(p + 4));
        if (inr) v2 = __ldcs((const float4*)(p + 8));
        if (inr) v3 = __ldcs((const float4*)(p + 12));
        float rv0 = 0.f, rv1 = 0.f;
        if (h0ok) rv0 = __ldcs(ph);
        if (h1ok) rv1 = __ldcs(ph + 1);

        float e[ELPL + 4];   // log2 window, t in [tbase-2, tbase+ELPL+2)
        e[2]  = __log2f(fmaf(gamma, v0.x, 1.0f));
        e[3]  = __log2f(fmaf(gamma, v0.y, 1.0f));
        e[4]  = __log2f(fmaf(gamma, v0.z, 1.0f));
        e[5]  = __log2f(fmaf(gamma, v0.w, 1.0f));
        e[6]  = __log2f(fmaf(gamma, v1.x, 1.0f));
        e[7]  = __log2f(fmaf(gamma, v1.y, 1.0f));
        e[8]  = __log2f(fmaf(gamma, v1.z, 1.0f));
        e[9]  = __log2f(fmaf(gamma, v1.w, 1.0f));
        e[10] = __log2f(fmaf(gamma, v2.x, 1.0f));
        e[11] = __log2f(fmaf(gamma, v2.y, 1.0f));
        e[12] = __log2f(fmaf(gamma, v2.z, 1.0f));
        e[13] = __log2f(fmaf(gamma, v2.w, 1.0f));
        e[14] = __log2f(fmaf(gamma, v3.x, 1.0f));
        e[15] = __log2f(fmaf(gamma, v3.y, 1.0f));
        e[16] = __log2f(fmaf(gamma, v3.z, 1.0f));
        e[17] = __log2f(fmaf(gamma, v3.w, 1.0f));

        // halo via shuffles; OOB neighbors carry 0 == zero padding
        e[0]        = __shfl_up_sync(0xffffffffu, e[ELPL], 1);
        e[1]        = __shfl_up_sync(0xffffffffu, e[ELPL + 1], 1);
        e[ELPL + 2] = __shfl_down_sync(0xffffffffu, e[2], 1);
        e[ELPL + 3] = __shfl_down_sync(0xffffffffu, e[3], 1);
        // edge fixup, branch-free: invalid rv=0 -> log2(fma(g,0,1)) = 0
        float h0 = __log2f(fmaf(gamma, rv0, 1.0f));
        float h1 = __log2f(fmaf(gamma, rv1, 1.0f));
        e[0]        = em ? h0 : e[0];
        e[1]        = em ? h1 : e[1];
        e[ELPL + 2] = (lane == 31) ? h0 : e[ELPL + 2];
        e[ELPL + 3] = (lane == 31) ? h1 : e[ELPL + 3];

#pragma unroll
        for (int j = 0; j < ELPL; ++j) {
            float s = db;
            s = fmaf(dw0, e[j],     s);
            s = fmaf(dw1, e[j + 1], s);
            s = fmaf(dw2, e[j + 2], s);
            s = fmaf(dw3, e[j + 3], s);
            s = fmaf(dw4, e[j + 4], s);
            acc[j] += fmaxf(s, 0.f);
        }

        p  += TQ;
        ph += TQ;
    }

    // combine the 4 warps' partial sums through smem
#pragma unroll
    for (int q = 0; q < 4; ++q)
        *(float4*)&sred[warp][ELPL * lane + 4 * q] =
            make_float4(acc[4*q], acc[4*q+1], acc[4*q+2], acc[4*q+3]);
    __syncthreads();

    {
        int i0 = 4 * tid;                      // 0..508
        int t  = t0 + i0;
        if (t < TQ) {                          // TQ%4==0 -> whole float4 in range
            float4 r0 = *(const float4*)&sred[0][i0];
            float4 r1 = *(const float4*)&sred[1][i0];
            float4 r2 = *(const float4*)&sred[2][i0];
            float4 r3 = *(const float4*)&sred[3][i0];
            float4 o;
            o.x = (r0.x + r1.x) + (r2.x + r3.x);
            o.y = (r0.y + r1.y) + (r2.y + r3.y);
            o.z = (r0.z + r1.z) + (r2.z + r3.z);
            o.w = (r0.w + r1.w) + (r2.w + r3.w);
            *(float4*)&g_xp[((size_t)b * NBQ + band) * TQ + t] = o;
        }
    }
    cudaTriggerProgrammaticLaunchCompletion();
}

// ============================================================================
// K2: xp -> xg, C, per-batch scalar atomics. Register-blocked float4 phases.
//   PDL trigger at ENTRY: k3's blocks launch + preload weights while k2 runs
//   (k3 still gridsyncs on k2 before touching its output).
// ============================================================================
__global__ __launch_bounds__(256) void k2_xgC(
    const float* __restrict__ la_w, const float* __restrict__ la_b,
    const float* __restrict__ mix_w,
    const float* __restrict__ g_w,  const float* __restrict__ g_b,
    const float* __restrict__ fg_w)
{
    __shared__ __align__(16) float sxp[NBQ][552];  // 550 valid + pad
    __shared__ __align__(16) float sxm[544];       // 540 valid + pad
    __shared__ __align__(16) float sxg[528];       // 526 valid + pad
    __shared__ float wlaw[NBQ * NLA], wg[NG], wfg[NG], wlab[NBQ], wmw[NBQ];

    cudaTriggerProgrammaticLaunchCompletion();   // let k3 launch early

    const int t0  = blockIdx.x * TT2K;
    const int b   = blockIdx.y;
    const int tid = threadIdx.x;

    // prologue: kernel inputs only (safe before the PDL dependency point)
    if (tid < NBQ * NLA) wlaw[tid] = la_w[tid];
    if (tid < NG)        { wg[tid] = g_w[tid]; wfg[tid] = fg_w[tid]; }
    if (tid < NBQ)       { wlab[tid] = la_b[tid]; wmw[tid] = mix_w[tid]; }
    const float gb = g_b[0];

    cudaGridDependencySynchronize();   // wait for k1's g_xp / scalar init

    for (int n = tid; n < NBQ * 550; n += 256) {
        int band = n / 550;
        int i    = n - band * 550;
        int t    = t0 - H3 + i;
        sxp[band][i] = (t >= 0 && t < TQ)
                     ? g_xp[((size_t)b * NBQ + band) * TQ + t] : 0.0f;
    }
    __syncthreads();

    // xm groups: thread t<135 computes xm[4t .. 4t+3] (t of xm[i] = t0-14+i)
    if (tid < 135) {
        const int i0 = 4 * tid;
        float xm0 = 0.f, xm1 = 0.f, xm2 = 0.f, xm3 = 0.f;
#pragma unroll
        for (int band = 0; band < NBQ; ++band) {
            float4 a0 = *(const float4*)&sxp[band][i0];
            float4 a1 = *(const float4*)&sxp[band][i0 + 4];
            float4 a2 = *(const float4*)&sxp[band][i0 + 8];
            float4 a3 = *(const float4*)&sxp[band][i0 + 12];
            float w[16] = {a0.x,a0.y,a0.z,a0.w, a1.x,a1.y,a1.z,a1.w,
                           a2.x,a2.y,a2.z,a2.w, a3.x,a3.y,a3.z,a3.w};
            const float lb = wlab[band], mw = wmw[band];
            float c0 = lb, c1 = lb, c2 = lb, c3 = lb;
#pragma unroll
            for (int j = 0; j < NLA; ++j) {
                float lw = wlaw[band * NLA + j];
                c0 = fmaf(lw, w[j],     c0);
                c1 = fmaf(lw, w[j + 1], c1);
                c2 = fmaf(lw, w[j + 2], c2);
                c3 = fmaf(lw, w[j + 3], c3);
            }
            xm0 = fmaf(mw, w[5] - c0, xm0);
            xm1 = fmaf(mw, w[6] - c1, xm1);
            xm2 = fmaf(mw, w[7] - c2, xm2);
            xm3 = fmaf(mw, w[8] - c3, xm3);
        }
        const int tb = t0 - 14 + i0;
        if (tb + 0 < 0 || tb + 0 >= TQ) xm0 = 0.f;
        if (tb + 1 < 0 || tb + 1 >= TQ) xm1 = 0.f;
        if (tb + 2 < 0 || tb + 2 >= TQ) xm2 = 0.f;
        if (tb + 3 < 0 || tb + 3 >= TQ) xm3 = 0.f;
        *(float4*)&sxm[i0] = make_float4(xm0, xm1, xm2, xm3);
    }
    __syncthreads();

    // xg groups: thread t<132 computes xg[4t .. 4t+3] (t of xg[j] = t0-7+j)
    if (tid < 132) {
        const int j0 = 4 * tid;
        float4 a0 = *(const float4*)&sxm[j0];
        float4 a1 = *(const float4*)&sxm[j0 + 4];
        float4 a2 = *(const float4*)&sxm[j0 + 8];
        float4 a3 = *(const float4*)&sxm[j0 + 12];
        float4 a4 = *(const float4*)&sxm[j0 + 16];
        float w[20] = {a0.x,a0.y,a0.z,a0.w, a1.x,a1.y,a1.z,a1.w,
                       a2.x,a2.y,a2.z,a2.w, a3.x,a3.y,a3.z,a3.w,
                       a4.x,a4.y,a4.z,a4.w};
        float s0 = gb, s1 = gb, s2 = gb, s3 = gb;
#pragma unroll
        for (int k = 0; k < NG; ++k) {
            float g = wg[k];
            s0 = fmaf(g, w[k],     s0);
            s1 = fmaf(g, w[k + 1], s1);
            s2 = fmaf(g, w[k + 2], s2);
            s3 = fmaf(g, w[k + 3], s3);
        }
        const int tb = t0 - 7 + j0;
        float x0 = (tb + 0 >= 0 && tb + 0 < TQ && j0 + 0 < 526) ? fmaxf(s0, 0.f) : 0.f;
        float x1 = (tb + 1 >= 0 && tb + 1 < TQ && j0 + 1 < 526) ? fmaxf(s1, 0.f) : 0.f;
        float x2 = (tb + 2 >= 0 && tb + 2 < TQ && j0 + 2 < 526) ? fmaxf(s2, 0.f) : 0.f;
        float x3 = (tb + 3 >= 0 && tb + 3 < TQ && j0 + 3 < 526) ? fmaxf(s3, 0.f) : 0.f;
        *(float4*)&sxg[j0] = make_float4(x0, x1, x2, x3);
    }
    __syncthreads();

    // C + emit phase: thread t<128 handles t = t0+4t .. +3 (group fully
    // valid or fully invalid since TQ % 4 == 0).
    float lmaxg = 0.0f;
    float lmaxC = -CUDART_INF_F, lminC = CUDART_INF_F;
    if (tid < 128) {
        const int i0 = 4 * tid;
        const int t  = t0 + i0;
        if (t < TQ) {
            float4 a0 = *(const float4*)&sxg[i0];
            float4 a1 = *(const float4*)&sxg[i0 + 4];
            float4 a2 = *(const float4*)&sxg[i0 + 8];
            float4 a3 = *(const float4*)&sxg[i0 + 12];
            float4 a4 = *(const float4*)&sxg[i0 + 16];
            float w[20] = {a0.x,a0.y,a0.z,a0.w, a1.x,a1.y,a1.z,a1.w,
                           a2.x,a2.y,a2.z,a2.w, a3.x,a3.y,a3.z,a3.w,
                           a4.x,a4.y,a4.z,a4.w};
            float C0 = 0.f, C1 = 0.f, C2 = 0.f, C3 = 0.f;
#pragma unroll
            for (int k = 0; k < NG; ++k) {
                float f = wfg[k];
                C0 = fmaf(f, w[k],     C0);
                C1 = fmaf(f, w[k + 1], C1);
                C2 = fmaf(f, w[k + 2], C2);
                C3 = fmaf(f, w[k + 3], C3);
            }
            size_t n4 = ((size_t)b * TQ + t) / 4;
            ((float4*)g_xg)[n4] = make_float4(w[7], w[8], w[9], w[10]);
            ((float4*)g_C)[n4]  = make_float4(C0, C1, C2, C3);
            lmaxg = fmaxf(fmaxf(w[7], w[8]), fmaxf(w[9], w[10]));
            // interior max/min of C (t in [7, TQ-7))
            if (t + 0 >= 7 && t + 0 < TQ - 7) { lmaxC = fmaxf(lmaxC, C0); lminC = fminf(lminC, C0); }
            if (t + 1 >= 7 && t + 1 < TQ - 7) { lmaxC = fmaxf(lmaxC, C1); lminC = fminf(lminC, C1); }
            if (t + 2 >= 7 && t + 2 < TQ - 7) { lmaxC = fmaxf(lmaxC, C2); lminC = fminf(lminC, C2); }
            if (t + 3 >= 7 && t + 3 < TQ - 7) { lmaxC = fmaxf(lmaxC, C3); lminC = fminf(lminC, C3); }
        }
    }
    int kmax = f2key(lmaxC), kmin = f2key(lminC);
#pragma unroll
    for (int off = 16; off; off >>= 1) {
        lmaxg = fmaxf(lmaxg, __shfl_xor_sync(0xffffffffu, lmaxg, off));
        kmax  = max(kmax, __shfl_xor_sync(0xffffffffu, kmax, off));
        kmin  = min(kmin, __shfl_xor_sync(0xffffffffu, kmin, off));
    }
    if ((tid & 31) == 0) {
        atomicMax(&g_maxxg_bits[b], __float_as_int(lmaxg));  // xg >= 0
        atomicMax(&g_maxC_key[b], kmax);
        atomicMin(&g_minC_key[b], kmin);
    }
}

// ============================================================================
// K3: pure elementwise finale, float4-wide (1 float4 per thread).
// ============================================================================
__global__ __launch_bounds__(128) void k3_out(
    const float* __restrict__ fc_w, const float* __restrict__ fc_b,
    const float* __restrict__ fg_w, const float* __restrict__ fg_b,
    float* __restrict__ out_sf, float* __restrict__ out_fn)
{
    __shared__ float swfg[NG];
    __shared__ float sc[6];   // inv, a, dn, d_interior, cb, fgb

    const int b   = blockIdx.y;
    const int tid = threadIdx.x;
    const int t4  = blockIdx.x * 128 + tid;   // float4 index
    const int t   = 4 * t4;

    if (tid < NG) swfg[tid] = fg_w[tid];      // input-only prologue

    cudaGridDependencySynchronize();          // wait for k2's xg/C/scalars
    __syncthreads();

    if (tid == 0) {
        const float cb  = fc_b[0];
        const float fgb = fg_b[0];
        float S = fc_w[0] + fc_w[1] + fc_w[2] + fc_w[3];
        float maxxg = __int_as_float(g_maxxg_bits[b]);
        float inv = 1.0f / (maxxg + EPSQ);
        float a   = S * inv;
        float Wfull = 0.0f;
#pragma unroll
        for (int k = 0; k < NG; ++k) Wfull += swfg[k];
        float d_int = fmaf(cb, Wfull, fgb);
        float maxC = key2f(g_maxC_key[b]);
        float minC = key2f(g_minC_key[b]);
        float best = fmaf(a, (a >= 0.0f) ? maxC : minC, d_int);
        // 14 edge positions: t in [0,7) U [T-7, T)
#pragma unroll
        for (int e = 0; e < 14; ++e) {
            int tt = (e < 7) ? e : (TQ - 14 + e);
            float Wt = 0.0f;
#pragma unroll
            for (int k = 0; k < NG; ++k) {
                int p = tt - 7 + k;
                if (p >= 0 && p < TQ) Wt += swfg[k];
            }
            float fsv = fmaf(a, g_C[(size_t)b * TQ + tt], fmaf(cb, Wt, fgb));
            best = fmaxf(best, fsv);
        }
        float famax = 1.0f / (1.0f + __expf(-best));
        sc[0] = inv;
        sc[1] = a;
        sc[2] = 1.0f / (famax + EPSQ);
        sc[3] = d_int;
        sc[4] = cb;
        sc[5] = fgb;
    }
    __syncthreads();

    if (t < TQ) {   // TQ % 4 == 0 -> full float4 in range
        size_t n4 = (size_t)b * (TQ / 4) + t4;
        float4 xg4 = ((const float4*)g_xg)[n4];
        float4 C4  = ((const float4*)g_C)[n4];
        const float inv = sc[0], a = sc[1], dn = sc[2], d_int = sc[3];

        float4 sf4;
        sf4.x = xg4.x * inv; sf4.y = xg4.y * inv;
        sf4.z = xg4.z * inv; sf4.w = xg4.w * inv;
        ((float4*)out_sf)[n4] = sf4;

        float d0 = d_int, d1 = d_int, d2 = d_int, d3 = d_int;
        if (t < 7 || t + 3 >= TQ - 7) {   // rare edge slow path
            const float cb = sc[4], fgb = sc[5];
#pragma unroll
            for (int q = 0; q < 4; ++q) {
                int tt = t + q;
                float Wt = 0.0f;
#pragma unroll
                for (int k = 0; k < NG; ++k) {
                    int p = tt - 7 + k;
                    if (p >= 0 && p < TQ) Wt += swfg[k];
                }
                float dv = fmaf(cb, Wt, fgb);
                if (q == 0) d0 = dv; else if (q == 1) d1 = dv;
                else if (q == 2) d2 = dv; else d3 = dv;
            }
        }
        float4 o;
        o.x = dn / (1.0f + __expf(-fmaf(a, C4.x, d0)));
        o.y = dn / (1.0f + __expf(-fmaf(a, C4.y, d1)));
        o.z = dn / (1.0f + __expf(-fmaf(a, C4.z, d2)));
        o.w = dn / (1.0f + __expf(-fmaf(a, C4.w, d3)));
        ((float4*)out_fn)[n4] = o;
    }
}

// ============================================================================
extern "C" void kernel_launch(void* const* d_in, const int* in_sizes, int n_in,
                              void* d_out, int out_size)
{
    const float* x         = (const float*)d_in[0];
    const float* log_gamma = (const float*)d_in[1];
    const float* diff_w    = (const float*)d_in[2];
    const float* diff_b    = (const float*)d_in[3];
    const float* la_w      = (const float*)d_in[4];
    const float* la_b      = (const float*)d_in[5];
    const float* mix_w     = (const float*)d_in[6];
    const float* g_w       = (const float*)d_in[7];
    const float* g_b       = (const float*)d_in[8];
    const float* fc_w      = (const float*)d_in[9];
    const float* fc_b      = (const float*)d_in[10];
    const float* fg_w      = (const float*)d_in[11];
    const float* fg_b      = (const float*)d_in[12];
    float* out = (float*)d_out;

    dim3 g1((TQ + K1SPAN - 1) / K1SPAN, NBQ, BQ);  // 118 x 8 x 4
    k1_xp<<<g1, K1B>>>(x, log_gamma, diff_w, diff_b);

    // PDL attribute: k2/k3 may start early; they gate on
    // cudaGridDependencySynchronize() before touching predecessor output.
    cudaLaunchAttribute attr[1];
    attr[0].id = cudaLaunchAttributeProgrammaticStreamSerialization;
    attr[0].val.programmaticStreamSerializationAllowed = 1;

    {
        cudaLaunchConfig_t cfg = {};
        cfg.gridDim  = dim3(NTILE, BQ, 1);         // 118 x 4
        cfg.blockDim = dim3(256, 1, 1);
        cfg.stream   = (cudaStream_t)0;
        cfg.attrs    = attr;
        cfg.numAttrs = 1;
        cudaLaunchKernelEx(&cfg, k2_xgC, la_w, la_b, mix_w, g_w, g_b, fg_w);
    }
    {
        cudaLaunchConfig_t cfg = {};
        cfg.gridDim  = dim3((TQ / 4 + 127) / 128, BQ, 1);  // 118 x 4
        cfg.blockDim = dim3(128, 1, 1);
        cfg.stream   = (cudaStream_t)0;
        cfg.attrs    = attr;
        cfg.numAttrs = 1;
        cudaLaunchKernelEx(&cfg, k3_out, fc_w, fc_b, fg_w, fg_b,
                           out, out + (size_t)BQ * TQ);
    }
}

// round 15
// speedup vs baseline: 1.3030x; 1.0234x over previous
#include <cuda_runtime.h>
#include <math_constants.h>

// Problem dims (fixed instance)
#define BQ  4
#define FQ  256
#define TQ  60000
#define NBQ 8
#define FB  32
#define ND  5
#define NLA 11
#define NG  15
#define EPSQ 1e-8f
#define LN2F 0.6931471805599453f

// K1 geometry: block = 128 thr (4 warps) on one 512-t span;
// warps split the 32 freq rows 8 each; lane owns 16 consecutive t.
#define ELPL   16
#define K1W    4
#define K1B    (K1W * 32)        // 128
#define K1SPAN (ELPL * 32)       // 512
#define ROWS_PER_WARP (FB / K1W) // 8

#define TT2K 512   // k2 tile
#define H3   19    // halo: 5 (moving-avg) + 7 (gauss) + 7 (fuse gauss)
#define NTILE ((TQ + TT2K - 1) / TT2K)   // 118
#define NV4   138  // float4 loads per band: covers logical [-1, 551)

// ---- scratch (static device arrays; no allocation) ----
__device__ __align__(16) float g_xp[BQ * NBQ * TQ];
__device__ __align__(16) float g_xg[BQ * TQ];
__device__ __align__(16) float g_C[BQ * TQ];
__device__ int   g_maxxg_bits[BQ];      // xg >= 0 -> plain int max works
__device__ int   g_maxC_key[BQ];        // monotone float->int keys
__device__ int   g_minC_key[BQ];

// monotone involution float <-> signed-int key (total order incl. negatives)
__device__ __forceinline__ int f2key(float v) {
    int u = __float_as_int(v);
    return (u >= 0) ? u : (u ^ 0x7FFFFFFF);
}
__device__ __forceinline__ float key2f(int k) {
    int u = (k >= 0) ? k : (k ^ 0x7FFFFFFF);
    return __int_as_float(u);
}

// ============================================================================
// K1: x [B,F,T] -> xp [B,NB,T]   (FROZEN — R8/R12-identical + PDL trigger)
// ============================================================================
__global__ __launch_bounds__(K1B, 10) void k1_xp(
    const float* __restrict__ x,
    const float* __restrict__ log_gamma,
    const float* __restrict__ diff_w,
    const float* __restrict__ diff_b)
{
    __shared__ float sred[K1W][K1SPAN];

    const int tid = threadIdx.x;
    // fold scalar init here (tail reads these only after k1 completes)
    if (blockIdx.x == 0 && blockIdx.y == 0 && blockIdx.z == 0 && tid < BQ) {
        g_maxxg_bits[tid] = 0;                     // xg >= 0
        g_maxC_key[tid]   = (int)0x80000000;       // -> -inf
        g_minC_key[tid]   = 0x7FFFFFFF;            // -> +inf
    }

    const int warp = tid >> 5;
    const int lane = tid & 31;
    const int band = blockIdx.y;
    const int b    = blockIdx.z;
    const int t0   = blockIdx.x * K1SPAN;
    const int tbase = t0 + ELPL * lane;
    const bool inr  = (tbase < TQ);       // TQ % 16 == 0 -> all 16 in range

    const float gamma = __expf(log_gamma[band]);
    // ln2 folded into the diff taps: conv(ln y) = sum (dw*ln2) * log2(y)
    const float dw0 = diff_w[band * ND + 0] * LN2F;
    const float dw1 = diff_w[band * ND + 1] * LN2F;
    const float dw2 = diff_w[band * ND + 2] * LN2F;
    const float dw3 = diff_w[band * ND + 3] * LN2F;
    const float dw4 = diff_w[band * ND + 4] * LN2F;
    const float db  = diff_b[band];

    // per-lane row pointer (bumped by TQ per row); halo pointer alongside
    const float* p = x + ((size_t)b * FQ + (size_t)band * FB
                          + (size_t)warp * ROWS_PER_WARP) * TQ + tbase;
    const bool  em  = (lane == 0);
    const float* ph = p + (em ? -2 : ELPL);
    // loop-invariant halo validity (tbase is a multiple of 16)
    const bool h0ok = (em && tbase >= 2) ||
                      (lane == 31 && inr && (tbase + ELPL     < TQ));
    const bool h1ok = (em && tbase >= 2) ||
                      (lane == 31 && inr && (tbase + ELPL + 1 < TQ));

    float acc[ELPL];
#pragma unroll
    for (int j = 0; j < ELPL; ++j) acc[j] = 0.f;

#pragma unroll 1
    for (int f = 0; f < ROWS_PER_WARP; ++f) {
        float4 v0 = {0.f,0.f,0.f,0.f}, v1 = v0, v2 = v0, v3 = v0;
        if (inr) v0 = __ldcs((const float4*)(p));
        if (inr) v1 = __ldcs((const float4*)(p + 4));
        if (inr) v2 = __ldcs((const float4*)(p + 8));
        if (inr) v3 = __ldcs((const float4*)(p + 12));
        float rv0 = 0.f, rv1 = 0.f;
        if (h0ok) rv0 = __ldcs(ph);
        if (h1ok) rv1 = __ldcs(ph + 1);

        float e[ELPL + 4];   // log2 window, t in [tbase-2, tbase+ELPL+2)
        e[2]  = __log2f(fmaf(gamma, v0.x, 1.0f));
        e[3]  = __log2f(fmaf(gamma, v0.y, 1.0f));
        e[4]  = __log2f(fmaf(gamma, v0.z, 1.0f));
        e[5]  = __log2f(fmaf(gamma, v0.w, 1.0f));
        e[6]  = __log2f(fmaf(gamma, v1.x, 1.0f));
        e[7]  = __log2f(fmaf(gamma, v1.y, 1.0f));
        e[8]  = __log2f(fmaf(gamma, v1.z, 1.0f));
        e[9]  = __log2f(fmaf(gamma, v1.w, 1.0f));
        e[10] = __log2f(fmaf(gamma, v2.x, 1.0f));
        e[11] = __log2f(fmaf(gamma, v2.y, 1.0f));
        e[12] = __log2f(fmaf(gamma, v2.z, 1.0f));
        e[13] = __log2f(fmaf(gamma, v2.w, 1.0f));
        e[14] = __log2f(fmaf(gamma, v3.x, 1.0f));
        e[15] = __log2f(fmaf(gamma, v3.y, 1.0f));
        e[16] = __log2f(fmaf(gamma, v3.z, 1.0f));
        e[17] = __log2f(fmaf(gamma, v3.w, 1.0f));

        // halo via shuffles; OOB neighbors carry 0 == zero padding
        e[0]        = __shfl_up_sync(0xffffffffu, e[ELPL], 1);
        e[1]        = __shfl_up_sync(0xffffffffu, e[ELPL + 1], 1);
        e[ELPL + 2] = __shfl_down_sync(0xffffffffu, e[2], 1);
        e[ELPL + 3] = __shfl_down_sync(0xffffffffu, e[3], 1);
        // edge fixup, branch-free: invalid rv=0 -> log2(fma(g,0,1)) = 0
        float h0 = __log2f(fmaf(gamma, rv0, 1.0f));
        float h1 = __log2f(fmaf(gamma, rv1, 1.0f));
        e[0]        = em ? h0 : e[0];
        e[1]        = em ? h1 : e[1];
        e[ELPL + 2] = (lane == 31) ? h0 : e[ELPL + 2];
        e[ELPL + 3] = (lane == 31) ? h1 : e[ELPL + 3];

#pragma unroll
        for (int j = 0; j < ELPL; ++j) {
            float s = db;
            s = fmaf(dw0, e[j],     s);
            s = fmaf(dw1, e[j + 1], s);
            s = fmaf(dw2, e[j + 2], s);
            s = fmaf(dw3, e[j + 3], s);
            s = fmaf(dw4, e[j + 4], s);
            acc[j] += fmaxf(s, 0.f);
        }

        p  += TQ;
        ph += TQ;
    }

    // combine the 4 warps' partial sums through smem
#pragma unroll
    for (int q = 0; q < 4; ++q)
        *(float4*)&sred[warp][ELPL * lane + 4 * q] =
            make_float4(acc[4*q], acc[4*q+1], acc[4*q+2], acc[4*q+3]);
    __syncthreads();

    {
        int i0 = 4 * tid;                      // 0..508
        int t  = t0 + i0;
        if (t < TQ) {                          // TQ%4==0 -> whole float4 in range
            float4 r0 = *(const float4*)&sred[0][i0];
            float4 r1 = *(const float4*)&sred[1][i0];
            float4 r2 = *(const float4*)&sred[2][i0];
            float4 r3 = *(const float4*)&sred[3][i0];
            float4 o;
            o.x = (r0.x + r1.x) + (r2.x + r3.x);
            o.y = (r0.y + r1.y) + (r2.y + r3.y);
            o.z = (r0.z + r1.z) + (r2.z + r3.z);
            o.w = (r0.w + r1.w) + (r2.w + r3.w);
            *(float4*)&g_xp[((size_t)b * NBQ + band) * TQ + t] = o;
        }
    }
    cudaTriggerProgrammaticLaunchCompletion();
}

// ============================================================================
// K2: xp -> xg, C, per-batch scalar atomics. Register-blocked float4 phases.
//   Fill phase vectorized: aligned float4 LDGs (t == 0 mod 4), scalar STS
//   scatter into the logical [t0-19, t0+531) smem window.
//   PDL trigger at END (R12 discipline — entry-trigger regressed in R14).
// ============================================================================
__global__ __launch_bounds__(256) void k2_xgC(
    const float* __restrict__ la_w, const float* __restrict__ la_b,
    const float* __restrict__ mix_w,
    const float* __restrict__ g_w,  const float* __restrict__ g_b,
    const float* __restrict__ fg_w)
{
    __shared__ __align__(16) float sxp[NBQ][552];  // 550 valid + pad
    __shared__ __align__(16) float sxm[544];       // 540 valid + pad
    __shared__ __align__(16) float sxg[528];       // 526 valid + pad
    __shared__ float wlaw[NBQ * NLA], wg[NG], wfg[NG], wlab[NBQ], wmw[NBQ];

    const int t0  = blockIdx.x * TT2K;
    const int b   = blockIdx.y;
    const int tid = threadIdx.x;

    // prologue: kernel inputs only (safe before the PDL dependency point)
    if (tid < NBQ * NLA) wlaw[tid] = la_w[tid];
    if (tid < NG)        { wg[tid] = g_w[tid]; wfg[tid] = fg_w[tid]; }
    if (tid < NBQ)       { wlab[tid] = la_b[tid]; wmw[tid] = mix_w[tid]; }
    const float gb = g_b[0];

    cudaGridDependencySynchronize();   // wait for k1's g_xp / scalar init

    // Fill: logical idx L in [0,550) maps t = t0-19+L. Aligned float4 at
    // t = t0-20+4k (k in [0,NV4)) covers L = 4k-1..4k+2. Validity is uniform
    // within a float4 (t and TQ are multiples of 4); OOB float4s contribute 0.
    for (int n = tid; n < NBQ * NV4; n += 256) {
        int band = n / NV4;
        int k    = n - band * NV4;
        int t    = t0 - 20 + 4 * k;
        float4 v = make_float4(0.f, 0.f, 0.f, 0.f);
        if (t >= 0 && t < TQ)
            v = *(const float4*)&g_xp[((size_t)b * NBQ + band) * TQ + t];
        int L = 4 * k - 1;
        if (L >= 0)        sxp[band][L]     = v.x;
        if (L + 1 < 550)   sxp[band][L + 1] = v.y;
        if (L + 2 < 550)   sxp[band][L + 2] = v.z;
        if (L + 3 < 550)   sxp[band][L + 3] = v.w;
    }
    __syncthreads();

    // xm groups: thread t<135 computes xm[4t .. 4t+3] (t of xm[i] = t0-14+i)
    if (tid < 135) {
        const int i0 = 4 * tid;
        float xm0 = 0.f, xm1 = 0.f, xm2 = 0.f, xm3 = 0.f;
#pragma unroll
        for (int band = 0; band < NBQ; ++band) {
            float4 a0 = *(const float4*)&sxp[band][i0];
            float4 a1 = *(const float4*)&sxp[band][i0 + 4];
            float4 a2 = *(const float4*)&sxp[band][i0 + 8];
            float4 a3 = *(const float4*)&sxp[band][i0 + 12];
            float w[16] = {a0.x,a0.y,a0.z,a0.w, a1.x,a1.y,a1.z,a1.w,
                           a2.x,a2.y,a2.z,a2.w, a3.x,a3.y,a3.z,a3.w};
            const float lb = wlab[band], mw = wmw[band];
            float c0 = lb, c1 = lb, c2 = lb, c3 = lb;
#pragma unroll
            for (int j = 0; j < NLA; ++j) {
                float lw = wlaw[band * NLA + j];
                c0 = fmaf(lw, w[j],     c0);
                c1 = fmaf(lw, w[j + 1], c1);
                c2 = fmaf(lw, w[j + 2], c2);
                c3 = fmaf(lw, w[j + 3], c3);
            }
            xm0 = fmaf(mw, w[5] - c0, xm0);
            xm1 = fmaf(mw, w[6] - c1, xm1);
            xm2 = fmaf(mw, w[7] - c2, xm2);
            xm3 = fmaf(mw, w[8] - c3, xm3);
        }
        const int tb = t0 - 14 + i0;
        if (tb + 0 < 0 || tb + 0 >= TQ) xm0 = 0.f;
        if (tb + 1 < 0 || tb + 1 >= TQ) xm1 = 0.f;
        if (tb + 2 < 0 || tb + 2 >= TQ) xm2 = 0.f;
        if (tb + 3 < 0 || tb + 3 >= TQ) xm3 = 0.f;
        *(float4*)&sxm[i0] = make_float4(xm0, xm1, xm2, xm3);
    }
    __syncthreads();

    // xg groups: thread t<132 computes xg[4t .. 4t+3] (t of xg[j] = t0-7+j)
    if (tid < 132) {
        const int j0 = 4 * tid;
        float4 a0 = *(const float4*)&sxm[j0];
        float4 a1 = *(const float4*)&sxm[j0 + 4];
        float4 a2 = *(const float4*)&sxm[j0 + 8];
        float4 a3 = *(const float4*)&sxm[j0 + 12];
        float4 a4 = *(const float4*)&sxm[j0 + 16];
        float w[20] = {a0.x,a0.y,a0.z,a0.w, a1.x,a1.y,a1.z,a1.w,
                       a2.x,a2.y,a2.z,a2.w, a3.x,a3.y,a3.z,a3.w,
                       a4.x,a4.y,a4.z,a4.w};
        float s0 = gb, s1 = gb, s2 = gb, s3 = gb;
#pragma unroll
        for (int k = 0; k < NG; ++k) {
            float g = wg[k];
            s0 = fmaf(g, w[k],     s0);
            s1 = fmaf(g, w[k + 1], s1);
            s2 = fmaf(g, w[k + 2], s2);
            s3 = fmaf(g, w[k + 3], s3);
        }
        const int tb = t0 - 7 + j0;
        float x0 = (tb + 0 >= 0 && tb + 0 < TQ && j0 + 0 < 526) ? fmaxf(s0, 0.f) : 0.f;
        float x1 = (tb + 1 >= 0 && tb + 1 < TQ && j0 + 1 < 526) ? fmaxf(s1, 0.f) : 0.f;
        float x2 = (tb + 2 >= 0 && tb + 2 < TQ && j0 + 2 < 526) ? fmaxf(s2, 0.f) : 0.f;
        float x3 = (tb + 3 >= 0 && tb + 3 < TQ && j0 + 3 < 526) ? fmaxf(s3, 0.f) : 0.f;
        *(float4*)&sxg[j0] = make_float4(x0, x1, x2, x3);
    }
    __syncthreads();

    // C + emit phase: thread t<128 handles t = t0+4t .. +3 (group fully
    // valid or fully invalid since TQ % 4 == 0).
    float lmaxg = 0.0f;
    float lmaxC = -CUDART_INF_F, lminC = CUDART_INF_F;
    if (tid < 128) {
        const int i0 = 4 * tid;
        const int t  = t0 + i0;
        if (t < TQ) {
            float4 a0 = *(const float4*)&sxg[i0];
            float4 a1 = *(const float4*)&sxg[i0 + 4];
            float4 a2 = *(const float4*)&sxg[i0 + 8];
            float4 a3 = *(const float4*)&sxg[i0 + 12];
            float4 a4 = *(const float4*)&sxg[i0 + 16];
            float w[20] = {a0.x,a0.y,a0.z,a0.w, a1.x,a1.y,a1.z,a1.w,
                           a2.x,a2.y,a2.z,a2.w, a3.x,a3.y,a3.z,a3.w,
                           a4.x,a4.y,a4.z,a4.w};
            float C0 = 0.f, C1 = 0.f, C2 = 0.f, C3 = 0.f;
#pragma unroll
            for (int k = 0; k < NG; ++k) {
                float f = wfg[k];
                C0 = fmaf(f, w[k],     C0);
                C1 = fmaf(f, w[k + 1], C1);
                C2 = fmaf(f, w[k + 2], C2);
                C3 = fmaf(f, w[k + 3], C3);
            }
            size_t n4 = ((size_t)b * TQ + t) / 4;
            ((float4*)g_xg)[n4] = make_float4(w[7], w[8], w[9], w[10]);
            ((float4*)g_C)[n4]  = make_float4(C0, C1, C2, C3);
            lmaxg = fmaxf(fmaxf(w[7], w[8]), fmaxf(w[9], w[10]));
            // interior max/min of C (t in [7, TQ-7))
            if (t + 0 >= 7 && t + 0 < TQ - 7) { lmaxC = fmaxf(lmaxC, C0); lminC = fminf(lminC, C0); }
            if (t + 1 >= 7 && t + 1 < TQ - 7) { lmaxC = fmaxf(lmaxC, C1); lminC = fminf(lminC, C1); }
            if (t + 2 >= 7 && t + 2 < TQ - 7) { lmaxC = fmaxf(lmaxC, C2); lminC = fminf(lminC, C2); }
            if (t + 3 >= 7 && t + 3 < TQ - 7) { lmaxC = fmaxf(lmaxC, C3); lminC = fminf(lminC, C3); }
        }
    }
    int kmax = f2key(lmaxC), kmin = f2key(lminC);
#pragma unroll
    for (int off = 16; off; off >>= 1) {
        lmaxg = fmaxf(lmaxg, __shfl_xor_sync(0xffffffffu, lmaxg, off));
        kmax  = max(kmax, __shfl_xor_sync(0xffffffffu, kmax, off));
        kmin  = min(kmin, __shfl_xor_sync(0xffffffffu, kmin, off));
    }
    if ((tid & 31) == 0) {
        atomicMax(&g_maxxg_bits[b], __float_as_int(lmaxg));  // xg >= 0
        atomicMax(&g_maxC_key[b], kmax);
        atomicMin(&g_minC_key[b], kmin);
    }
    cudaTriggerProgrammaticLaunchCompletion();
}

// ============================================================================
// K3: pure elementwise finale, float4-wide (1 float4 per thread).
// ============================================================================
__global__ __launch_bounds__(128) void k3_out(
    const float* __restrict__ fc_w, const float* __restrict__ fc_b,
    const float* __restrict__ fg_w, const float* __restrict__ fg_b,
    float* __restrict__ out_sf, float* __restrict__ out_fn)
{
    __shared__ float swfg[NG];
    __shared__ float sc[6];   // inv, a, dn, d_interior, cb, fgb

    const int b   = blockIdx.y;
    const int tid = threadIdx.x;
    const int t4  = blockIdx.x * 128 + tid;   // float4 index
    const int t   = 4 * t4;

    if (tid < NG) swfg[tid] = fg_w[tid];      // input-only prologue

    cudaGridDependencySynchronize();          // wait for k2's xg/C/scalars
    __syncthreads();

    if (tid == 0) {
        const float cb  = fc_b[0];
        const float fgb = fg_b[0];
        float S = fc_w[0] + fc_w[1] + fc_w[2] + fc_w[3];
        float maxxg = __int_as_float(g_maxxg_bits[b]);
        float inv = 1.0f / (maxxg + EPSQ);
        float a   = S * inv;
        float Wfull = 0.0f;
#pragma unroll
        for (int k = 0; k < NG; ++k) Wfull += swfg[k];
        float d_int = fmaf(cb, Wfull, fgb);
        float maxC = key2f(g_maxC_key[b]);
        float minC = key2f(g_minC_key[b]);
        float best = fmaf(a, (a >= 0.0f) ? maxC : minC, d_int);
        // 14 edge positions: t in [0,7) U [T-7, T)
#pragma unroll
        for (int e = 0; e < 14; ++e) {
            int tt = (e < 7) ? e : (TQ - 14 + e);
            float Wt = 0.0f;
#pragma unroll
            for (int k = 0; k < NG; ++k) {
                int p = tt - 7 + k;
                if (p >= 0 && p < TQ) Wt += swfg[k];
            }
            float fsv = fmaf(a, g_C[(size_t)b * TQ + tt], fmaf(cb, Wt, fgb));
            best = fmaxf(best, fsv);
        }
        float famax = 1.0f / (1.0f + __expf(-best));
        sc[0] = inv;
        sc[1] = a;
        sc[2] = 1.0f / (famax + EPSQ);
        sc[3] = d_int;
        sc[4] = cb;
        sc[5] = fgb;
    }
    __syncthreads();

    if (t < TQ) {   // TQ % 4 == 0 -> full float4 in range
        size_t n4 = (size_t)b * (TQ / 4) + t4;
        float4 xg4 = ((const float4*)g_xg)[n4];
        float4 C4  = ((const float4*)g_C)[n4];
        const float inv = sc[0], a = sc[1], dn = sc[2], d_int = sc[3];

        float4 sf4;
        sf4.x = xg4.x * inv; sf4.y = xg4.y * inv;
        sf4.z = xg4.z * inv; sf4.w = xg4.w * inv;
        ((float4*)out_sf)[n4] = sf4;

        float d0 = d_int, d1 = d_int, d2 = d_int, d3 = d_int;
        if (t < 7 || t + 3 >= TQ - 7) {   // rare edge slow path
            const float cb = sc[4], fgb = sc[5];
#pragma unroll
            for (int q = 0; q < 4; ++q) {
                int tt = t + q;
                float Wt = 0.0f;
#pragma unroll
                for (int k = 0; k < NG; ++k) {
                    int p = tt - 7 + k;
                    if (p >= 0 && p < TQ) Wt += swfg[k];
                }
                float dv = fmaf(cb, Wt, fgb);
                if (q == 0) d0 = dv; else if (q == 1) d1 = dv;
                else if (q == 2) d2 = dv; else d3 = dv;
            }
        }
        float4 o;
        o.x = dn / (1.0f + __expf(-fmaf(a, C4.x, d0)));
        o.y = dn / (1.0f + __expf(-fmaf(a, C4.y, d1)));
        o.z = dn / (1.0f + __expf(-fmaf(a, C4.z, d2)));
        o.w = dn / (1.0f + __expf(-fmaf(a, C4.w, d3)));
        ((float4*)out_fn)[n4] = o;
    }
}

// ============================================================================
extern "C" void kernel_launch(void* const* d_in, const int* in_sizes, int n_in,
                              void* d_out, int out_size)
{
    const float* x         = (const float*)d_in[0];
    const float* log_gamma = (const float*)d_in[1];
    const float* diff_w    = (const float*)d_in[2];
    const float* diff_b    = (const float*)d_in[3];
    const float* la_w      = (const float*)d_in[4];
    const float* la_b      = (const float*)d_in[5];
    const float* mix_w     = (const float*)d_in[6];
    const float* g_w       = (const float*)d_in[7];
    const float* g_b       = (const float*)d_in[8];
    const float* fc_w      = (const float*)d_in[9];
    const float* fc_b      = (const float*)d_in[10];
    const float* fg_w      = (const float*)d_in[11];
    const float* fg_b      = (const float*)d_in[12];
    float* out = (float*)d_out;

    dim3 g1((TQ + K1SPAN - 1) / K1SPAN, NBQ, BQ);  // 118 x 8 x 4
    k1_xp<<<g1, K1B>>>(x, log_gamma, diff_w, diff_b);

    // PDL attribute: k2/k3 may start early; they gate on
    // cudaGridDependencySynchronize() before touching predecessor output.
    cudaLaunchAttribute attr[1];
    attr[0].id = cudaLaunchAttributeProgrammaticStreamSerialization;
    attr[0].val.programmaticStreamSerializationAllowed = 1;

    {
        cudaLaunchConfig_t cfg = {};
        cfg.gridDim  = dim3(NTILE, BQ, 1);         // 118 x 4
        cfg.blockDim = dim3(256, 1, 1);
        cfg.stream   = (cudaStream_t)0;
        cfg.attrs    = attr;
        cfg.numAttrs = 1;
        cudaLaunchKernelEx(&cfg, k2_xgC, la_w, la_b, mix_w, g_w, g_b, fg_w);
    }
    {
        cudaLaunchConfig_t cfg = {};
        cfg.gridDim  = dim3((TQ / 4 + 127) / 128, BQ, 1);  // 118 x 4
        cfg.blockDim = dim3(128, 1, 1);
        cfg.stream   = (cudaStream_t)0;
        cfg.attrs    = attr;
        cfg.numAttrs = 1;
        cudaLaunchKernelEx(&cfg, k3_out, fc_w, fc_b, fg_w, fg_b,
                           out, out + (size_t)BQ * TQ);
    }
}

// round 16
// speedup vs baseline: 1.3625x; 1.0457x over previous
#include <cuda_runtime.h>
#include <math_constants.h>

// Problem dims (fixed instance)
#define BQ  4
#define FQ  256
#define TQ  60000
#define NBQ 8
#define FB  32
#define ND  5
#define NLA 11
#define NG  15
#define EPSQ 1e-8f
#define LN2F 0.6931471805599453f

// K1 geometry: block = 128 thr (4 warps) on one 512-t span;
// warps split the 32 freq rows 8 each; lane owns 16 consecutive t.
#define ELPL   16
#define K1W    4
#define K1B    (K1W * 32)        // 128
#define K1SPAN (ELPL * 32)       // 512
#define ROWS_PER_WARP (FB / K1W) // 8

#define TT2K 512   // k2 tile
#define H3   19    // halo: 5 (moving-avg) + 7 (gauss) + 7 (fuse gauss)
#define NTILE ((TQ + TT2K - 1) / TT2K)   // 118
#define NV4   138  // float4 loads per band: covers logical [-1, 551)

// ---- scratch (static device arrays; no allocation) ----
__device__ __align__(16) float g_xp[BQ * NBQ * TQ];
__device__ __align__(16) float g_xg[BQ * TQ];
__device__ __align__(16) float g_C[BQ * TQ];
__device__ int   g_maxxg_bits[BQ];      // xg >= 0 -> plain int max works
__device__ int   g_maxC_key[BQ];        // monotone float->int keys
__device__ int   g_minC_key[BQ];

// monotone involution float <-> signed-int key (total order incl. negatives)
__device__ __forceinline__ int f2key(float v) {
    int u = __float_as_int(v);
    return (u >= 0) ? u : (u ^ 0x7FFFFFFF);
}
__device__ __forceinline__ float key2f(int k) {
    int u = (k >= 0) ? k : (k ^ 0x7FFFFFFF);
    return __int_as_float(u);
}

// ============================================================================
// K1: x [B,F,T] -> xp [B,NB,T]
//   R8/R12 body; f-loop unrolled 2x so ptxas front-batches 2 rows' LDG.128s
//   (deeper MLP; 2nd row addressed at immediate +TQ offsets). launch_bounds
//   (128, 8) -> 64-reg budget, no spills.
// ============================================================================
__global__ __launch_bounds__(K1B, 8) void k1_xp(
    const float* __restrict__ x,
    const float* __restrict__ log_gamma,
    const float* __restrict__ diff_w,
    const float* __restrict__ diff_b)
{
    __shared__ float sred[K1W][K1SPAN];

    const int tid = threadIdx.x;
    // fold scalar init here (tail reads these only after k1 completes)
    if (blockIdx.x == 0 && blockIdx.y == 0 && blockIdx.z == 0 && tid < BQ) {
        g_maxxg_bits[tid] = 0;                     // xg >= 0
        g_maxC_key[tid]   = (int)0x80000000;       // -> -inf
        g_minC_key[tid]   = 0x7FFFFFFF;            // -> +inf
    }

    const int warp = tid >> 5;
    const int lane = tid & 31;
    const int band = blockIdx.y;
    const int b    = blockIdx.z;
    const int t0   = blockIdx.x * K1SPAN;
    const int tbase = t0 + ELPL * lane;
    const bool inr  = (tbase < TQ);       // TQ % 16 == 0 -> all 16 in range

    const float gamma = __expf(log_gamma[band]);
    // ln2 folded into the diff taps: conv(ln y) = sum (dw*ln2) * log2(y)
    const float dw0 = diff_w[band * ND + 0] * LN2F;
    const float dw1 = diff_w[band * ND + 1] * LN2F;
    const float dw2 = diff_w[band * ND + 2] * LN2F;
    const float dw3 = diff_w[band * ND + 3] * LN2F;
    const float dw4 = diff_w[band * ND + 4] * LN2F;
    const float db  = diff_b[band];

    // per-lane row pointer (bumped per unrolled pair); halo pointer alongside
    const float* p = x + ((size_t)b * FQ + (size_t)band * FB
                          + (size_t)warp * ROWS_PER_WARP) * TQ + tbase;
    const bool  em  = (lane == 0);
    const float* ph = p + (em ? -2 : ELPL);
    // loop-invariant halo validity (tbase is a multiple of 16)
    const bool h0ok = (em && tbase >= 2) ||
                      (lane == 31 && inr && (tbase + ELPL     < TQ));
    const bool h1ok = (em && tbase >= 2) ||
                      (lane == 31 && inr && (tbase + ELPL + 1 < TQ));

    float acc[ELPL];
#pragma unroll
    for (int j = 0; j < ELPL; ++j) acc[j] = 0.f;

#pragma unroll 2
    for (int f = 0; f < ROWS_PER_WARP; ++f) {
        float4 v0 = {0.f,0.f,0.f,0.f}, v1 = v0, v2 = v0, v3 = v0;
        if (inr) v0 = __ldcs((const float4*)(p));
        if (inr) v1 = __ldcs((const float4*)(p + 4));
        if (inr) v2 = __ldcs((const float4*)(p + 8));
        if (inr) v3 = __ldcs((const float4*)(p + 12));
        float rv0 = 0.f, rv1 = 0.f;
        if (h0ok) rv0 = __ldcs(ph);
        if (h1ok) rv1 = __ldcs(ph + 1);

        float e[ELPL + 4];   // log2 window, t in [tbase-2, tbase+ELPL+2)
        e[2]  = __log2f(fmaf(gamma, v0.x, 1.0f));
        e[3]  = __log2f(fmaf(gamma, v0.y, 1.0f));
        e[4]  = __log2f(fmaf(gamma, v0.z, 1.0f));
        e[5]  = __log2f(fmaf(gamma, v0.w, 1.0f));
        e[6]  = __log2f(fmaf(gamma, v1.x, 1.0f));
        e[7]  = __log2f(fmaf(gamma, v1.y, 1.0f));
        e[8]  = __log2f(fmaf(gamma, v1.z, 1.0f));
        e[9]  = __log2f(fmaf(gamma, v1.w, 1.0f));
        e[10] = __log2f(fmaf(gamma, v2.x, 1.0f));
        e[11] = __log2f(fmaf(gamma, v2.y, 1.0f));
        e[12] = __log2f(fmaf(gamma, v2.z, 1.0f));
        e[13] = __log2f(fmaf(gamma, v2.w, 1.0f));
        e[14] = __log2f(fmaf(gamma, v3.x, 1.0f));
        e[15] = __log2f(fmaf(gamma, v3.y, 1.0f));
        e[16] = __log2f(fmaf(gamma, v3.z, 1.0f));
        e[17] = __log2f(fmaf(gamma, v3.w, 1.0f));

        // halo via shuffles; OOB neighbors carry 0 == zero padding
        e[0]        = __shfl_up_sync(0xffffffffu, e[ELPL], 1);
        e[1]        = __shfl_up_sync(0xffffffffu, e[ELPL + 1], 1);
        e[ELPL + 2] = __shfl_down_sync(0xffffffffu, e[2], 1);
        e[ELPL + 3] = __shfl_down_sync(0xffffffffu, e[3], 1);
        // edge fixup, branch-free: invalid rv=0 -> log2(fma(g,0,1)) = 0
        float h0 = __log2f(fmaf(gamma, rv0, 1.0f));
        float h1 = __log2f(fmaf(gamma, rv1, 1.0f));
        e[0]        = em ? h0 : e[0];
        e[1]        = em ? h1 : e[1];
        e[ELPL + 2] = (lane == 31) ? h0 : e[ELPL + 2];
        e[ELPL + 3] = (lane == 31) ? h1 : e[ELPL + 3];

#pragma unroll
        for (int j = 0; j < ELPL; ++j) {
            float s = db;
            s = fmaf(dw0, e[j],     s);
            s = fmaf(dw1, e[j + 1], s);
            s = fmaf(dw2, e[j + 2], s);
            s = fmaf(dw3, e[j + 3], s);
            s = fmaf(dw4, e[j + 4], s);
            acc[j] += fmaxf(s, 0.f);
        }

        p  += TQ;
        ph += TQ;
    }

    // combine the 4 warps' partial sums through smem
#pragma unroll
    for (int q = 0; q < 4; ++q)
        *(float4*)&sred[warp][ELPL * lane + 4 * q] =
            make_float4(acc[4*q], acc[4*q+1], acc[4*q+2], acc[4*q+3]);
    __syncthreads();

    {
        int i0 = 4 * tid;                      // 0..508
        int t  = t0 + i0;
        if (t < TQ) {                          // TQ%4==0 -> whole float4 in range
            float4 r0 = *(const float4*)&sred[0][i0];
            float4 r1 = *(const float4*)&sred[1][i0];
            float4 r2 = *(const float4*)&sred[2][i0];
            float4 r3 = *(const float4*)&sred[3][i0];
            float4 o;
            o.x = (r0.x + r1.x) + (r2.x + r3.x);
            o.y = (r0.y + r1.y) + (r2.y + r3.y);
            o.z = (r0.z + r1.z) + (r2.z + r3.z);
            o.w = (r0.w + r1.w) + (r2.w + r3.w);
            *(float4*)&g_xp[((size_t)b * NBQ + band) * TQ + t] = o;
        }
    }
    cudaTriggerProgrammaticLaunchCompletion();
}

// ============================================================================
// K2: xp -> xg, C, per-batch scalar atomics. Register-blocked float4 phases.
//   Vectorized fill; PDL trigger at END (entry-trigger regressed in R14).
// ============================================================================
__global__ __launch_bounds__(256) void k2_xgC(
    const float* __restrict__ la_w, const float* __restrict__ la_b,
    const float* __restrict__ mix_w,
    const float* __restrict__ g_w,  const float* __restrict__ g_b,
    const float* __restrict__ fg_w)
{
    __shared__ __align__(16) float sxp[NBQ][552];  // 550 valid + pad
    __shared__ __align__(16) float sxm[544];       // 540 valid + pad
    __shared__ __align__(16) float sxg[528];       // 526 valid + pad
    __shared__ float wlaw[NBQ * NLA], wg[NG], wfg[NG], wlab[NBQ], wmw[NBQ];

    const int t0  = blockIdx.x * TT2K;
    const int b   = blockIdx.y;
    const int tid = threadIdx.x;

    // prologue: kernel inputs only (safe before the PDL dependency point)
    if (tid < NBQ * NLA) wlaw[tid] = la_w[tid];
    if (tid < NG)        { wg[tid] = g_w[tid]; wfg[tid] = fg_w[tid]; }
    if (tid < NBQ)       { wlab[tid] = la_b[tid]; wmw[tid] = mix_w[tid]; }
    const float gb = g_b[0];

    cudaGridDependencySynchronize();   // wait for k1's g_xp / scalar init

    // Fill: logical idx L in [0,550) maps t = t0-19+L. Aligned float4 at
    // t = t0-20+4k covers L = 4k-1..4k+2. Validity is uniform within a
    // float4 (t and TQ are multiples of 4); OOB float4s contribute 0.
    for (int n = tid; n < NBQ * NV4; n += 256) {
        int band = n / NV4;
        int k    = n - band * NV4;
        int t    = t0 - 20 + 4 * k;
        float4 v = make_float4(0.f, 0.f, 0.f, 0.f);
        if (t >= 0 && t < TQ)
            v = *(const float4*)&g_xp[((size_t)b * NBQ + band) * TQ + t];
        int L = 4 * k - 1;
        if (L >= 0)        sxp[band][L]     = v.x;
        if (L + 1 < 550)   sxp[band][L + 1] = v.y;
        if (L + 2 < 550)   sxp[band][L + 2] = v.z;
        if (L + 3 < 550)   sxp[band][L + 3] = v.w;
    }
    __syncthreads();

    // xm groups: thread t<135 computes xm[4t .. 4t+3] (t of xm[i] = t0-14+i)
    if (tid < 135) {
        const int i0 = 4 * tid;
        float xm0 = 0.f, xm1 = 0.f, xm2 = 0.f, xm3 = 0.f;
#pragma unroll
        for (int band = 0; band < NBQ; ++band) {
            float4 a0 = *(const float4*)&sxp[band][i0];
            float4 a1 = *(const float4*)&sxp[band][i0 + 4];
            float4 a2 = *(const float4*)&sxp[band][i0 + 8];
            float4 a3 = *(const float4*)&sxp[band][i0 + 12];
            float w[16] = {a0.x,a0.y,a0.z,a0.w, a1.x,a1.y,a1.z,a1.w,
                           a2.x,a2.y,a2.z,a2.w, a3.x,a3.y,a3.z,a3.w};
            const float lb = wlab[band], mw = wmw[band];
            float c0 = lb, c1 = lb, c2 = lb, c3 = lb;
#pragma unroll
            for (int j = 0; j < NLA; ++j) {
                float lw = wlaw[band * NLA + j];
                c0 = fmaf(lw, w[j],     c0);
                c1 = fmaf(lw, w[j + 1], c1);
                c2 = fmaf(lw, w[j + 2], c2);
                c3 = fmaf(lw, w[j + 3], c3);
            }
            xm0 = fmaf(mw, w[5] - c0, xm0);
            xm1 = fmaf(mw, w[6] - c1, xm1);
            xm2 = fmaf(mw, w[7] - c2, xm2);
            xm3 = fmaf(mw, w[8] - c3, xm3);
        }
        const int tb = t0 - 14 + i0;
        if (tb + 0 < 0 || tb + 0 >= TQ) xm0 = 0.f;
        if (tb + 1 < 0 || tb + 1 >= TQ) xm1 = 0.f;
        if (tb + 2 < 0 || tb + 2 >= TQ) xm2 = 0.f;
        if (tb + 3 < 0 || tb + 3 >= TQ) xm3 = 0.f;
        *(float4*)&sxm[i0] = make_float4(xm0, xm1, xm2, xm3);
    }
    __syncthreads();

    // xg groups: thread t<132 computes xg[4t .. 4t+3] (t of xg[j] = t0-7+j)
    if (tid < 132) {
        const int j0 = 4 * tid;
        float4 a0 = *(const float4*)&sxm[j0];
        float4 a1 = *(const float4*)&sxm[j0 + 4];
        float4 a2 = *(const float4*)&sxm[j0 + 8];
        float4 a3 = *(const float4*)&sxm[j0 + 12];
        float4 a4 = *(const float4*)&sxm[j0 + 16];
        float w[20] = {a0.x,a0.y,a0.z,a0.w, a1.x,a1.y,a1.z,a1.w,
                       a2.x,a2.y,a2.z,a2.w, a3.x,a3.y,a3.z,a3.w,
                       a4.x,a4.y,a4.z,a4.w};
        float s0 = gb, s1 = gb, s2 = gb, s3 = gb;
#pragma unroll
        for (int k = 0; k < NG; ++k) {
            float g = wg[k];
            s0 = fmaf(g, w[k],     s0);
            s1 = fmaf(g, w[k + 1], s1);
            s2 = fmaf(g, w[k + 2], s2);
            s3 = fmaf(g, w[k + 3], s3);
        }
        const int tb = t0 - 7 + j0;
        float x0 = (tb + 0 >= 0 && tb + 0 < TQ && j0 + 0 < 526) ? fmaxf(s0, 0.f) : 0.f;
        float x1 = (tb + 1 >= 0 && tb + 1 < TQ && j0 + 1 < 526) ? fmaxf(s1, 0.f) : 0.f;
        float x2 = (tb + 2 >= 0 && tb + 2 < TQ && j0 + 2 < 526) ? fmaxf(s2, 0.f) : 0.f;
        float x3 = (tb + 3 >= 0 && tb + 3 < TQ && j0 + 3 < 526) ? fmaxf(s3, 0.f) : 0.f;
        *(float4*)&sxg[j0] = make_float4(x0, x1, x2, x3);
    }
    __syncthreads();

    // C + emit phase: thread t<128 handles t = t0+4t .. +3 (group fully
    // valid or fully invalid since TQ % 4 == 0).
    float lmaxg = 0.0f;
    float lmaxC = -CUDART_INF_F, lminC = CUDART_INF_F;
    if (tid < 128) {
        const int i0 = 4 * tid;
        const int t  = t0 + i0;
        if (t < TQ) {
            float4 a0 = *(const float4*)&sxg[i0];
            float4 a1 = *(const float4*)&sxg[i0 + 4];
            float4 a2 = *(const float4*)&sxg[i0 + 8];
            float4 a3 = *(const float4*)&sxg[i0 + 12];
            float4 a4 = *(const float4*)&sxg[i0 + 16];
            float w[20] = {a0.x,a0.y,a0.z,a0.w, a1.x,a1.y,a1.z,a1.w,
                           a2.x,a2.y,a2.z,a2.w, a3.x,a3.y,a3.z,a3.w,
                           a4.x,a4.y,a4.z,a4.w};
            float C0 = 0.f, C1 = 0.f, C2 = 0.f, C3 = 0.f;
#pragma unroll
            for (int k = 0; k < NG; ++k) {
                float f = wfg[k];
                C0 = fmaf(f, w[k],     C0);
                C1 = fmaf(f, w[k + 1], C1);
                C2 = fmaf(f, w[k + 2], C2);
                C3 = fmaf(f, w[k + 3], C3);
            }
            size_t n4 = ((size_t)b * TQ + t) / 4;
            ((float4*)g_xg)[n4] = make_float4(w[7], w[8], w[9], w[10]);
            ((float4*)g_C)[n4]  = make_float4(C0, C1, C2, C3);
            lmaxg = fmaxf(fmaxf(w[7], w[8]), fmaxf(w[9], w[10]));
            // interior max/min of C (t in [7, TQ-7))
            if (t + 0 >= 7 && t + 0 < TQ - 7) { lmaxC = fmaxf(lmaxC, C0); lminC = fminf(lminC, C0); }
            if (t + 1 >= 7 && t + 1 < TQ - 7) { lmaxC = fmaxf(lmaxC, C1); lminC = fminf(lminC, C1); }
            if (t + 2 >= 7 && t + 2 < TQ - 7) { lmaxC = fmaxf(lmaxC, C2); lminC = fminf(lminC, C2); }
            if (t + 3 >= 7 && t + 3 < TQ - 7) { lmaxC = fmaxf(lmaxC, C3); lminC = fminf(lminC, C3); }
        }
    }
    int kmax = f2key(lmaxC), kmin = f2key(lminC);
#pragma unroll
    for (int off = 16; off; off >>= 1) {
        lmaxg = fmaxf(lmaxg, __shfl_xor_sync(0xffffffffu, lmaxg, off));
        kmax  = max(kmax, __shfl_xor_sync(0xffffffffu, kmax, off));
        kmin  = min(kmin, __shfl_xor_sync(0xffffffffu, kmin, off));
    }
    if ((tid & 31) == 0) {
        atomicMax(&g_maxxg_bits[b], __float_as_int(lmaxg));  // xg >= 0
        atomicMax(&g_maxC_key[b], kmax);
        atomicMin(&g_minC_key[b], kmin);
    }
    cudaTriggerProgrammaticLaunchCompletion();
}

// ============================================================================
// K3: pure elementwise finale, float4-wide (1 float4 per thread).
// ============================================================================
__global__ __launch_bounds__(128) void k3_out(
    const float* __restrict__ fc_w, const float* __restrict__ fc_b,
    const float* __restrict__ fg_w, const float* __restrict__ fg_b,
    float* __restrict__ out_sf, float* __restrict__ out_fn)
{
    __shared__ float swfg[NG];
    __shared__ float sc[6];   // inv, a, dn, d_interior, cb, fgb

    const int b   = blockIdx.y;
    const int tid = threadIdx.x;
    const int t4  = blockIdx.x * 128 + tid;   // float4 index
    const int t   = 4 * t4;

    if (tid < NG) swfg[tid] = fg_w[tid];      // input-only prologue

    cudaGridDependencySynchronize();          // wait for k2's xg/C/scalars
    __syncthreads();

    if (tid == 0) {
        const float cb  = fc_b[0];
        const float fgb = fg_b[0];
        float S = fc_w[0] + fc_w[1] + fc_w[2] + fc_w[3];
        float maxxg = __int_as_float(g_maxxg_bits[b]);
        float inv = 1.0f / (maxxg + EPSQ);
        float a   = S * inv;
        float Wfull = 0.0f;
#pragma unroll
        for (int k = 0; k < NG; ++k) Wfull += swfg[k];
        float d_int = fmaf(cb, Wfull, fgb);
        float maxC = key2f(g_maxC_key[b]);
        float minC = key2f(g_minC_key[b]);
        float best = fmaf(a, (a >= 0.0f) ? maxC : minC, d_int);
        // 14 edge positions: t in [0,7) U [T-7, T)
#pragma unroll
        for (int e = 0; e < 14; ++e) {
            int tt = (e < 7) ? e : (TQ - 14 + e);
            float Wt = 0.0f;
#pragma unroll
            for (int k = 0; k < NG; ++k) {
                int p = tt - 7 + k;
                if (p >= 0 && p < TQ) Wt += swfg[k];
            }
            float fsv = fmaf(a, g_C[(size_t)b * TQ + tt], fmaf(cb, Wt, fgb));
            best = fmaxf(best, fsv);
        }
        float famax = 1.0f / (1.0f + __expf(-best));
        sc[0] = inv;
        sc[1] = a;
        sc[2] = 1.0f / (famax + EPSQ);
        sc[3] = d_int;
        sc[4] = cb;
        sc[5] = fgb;
    }
    __syncthreads();

    if (t < TQ) {   // TQ % 4 == 0 -> full float4 in range
        size_t n4 = (size_t)b * (TQ / 4) + t4;
        float4 xg4 = ((const float4*)g_xg)[n4];
        float4 C4  = ((const float4*)g_C)[n4];
        const float inv = sc[0], a = sc[1], dn = sc[2], d_int = sc[3];

        float4 sf4;
        sf4.x = xg4.x * inv; sf4.y = xg4.y * inv;
        sf4.z = xg4.z * inv; sf4.w = xg4.w * inv;
        ((float4*)out_sf)[n4] = sf4;

        float d0 = d_int, d1 = d_int, d2 = d_int, d3 = d_int;
        if (t < 7 || t + 3 >= TQ - 7) {   // rare edge slow path
            const float cb = sc[4], fgb = sc[5];
#pragma unroll
            for (int q = 0; q < 4; ++q) {
                int tt = t + q;
                float Wt = 0.0f;
#pragma unroll
                for (int k = 0; k < NG; ++k) {
                    int p = tt - 7 + k;
                    if (p >= 0 && p < TQ) Wt += swfg[k];
                }
                float dv = fmaf(cb, Wt, fgb);
                if (q == 0) d0 = dv; else if (q == 1) d1 = dv;
                else if (q == 2) d2 = dv; else d3 = dv;
            }
        }
        float4 o;
        o.x = dn / (1.0f + __expf(-fmaf(a, C4.x, d0)));
        o.y = dn / (1.0f + __expf(-fmaf(a, C4.y, d1)));
        o.z = dn / (1.0f + __expf(-fmaf(a, C4.z, d2)));
        o.w = dn / (1.0f + __expf(-fmaf(a, C4.w, d3)));
        ((float4*)out_fn)[n4] = o;
    }
}

// ============================================================================
extern "C" void kernel_launch(void* const* d_in, const int* in_sizes, int n_in,
                              void* d_out, int out_size)
{
    const float* x         = (const float*)d_in[0];
    const float* log_gamma = (const float*)d_in[1];
    const float* diff_w    = (const float*)d_in[2];
    const float* diff_b    = (const float*)d_in[3];
    const float* la_w      = (const float*)d_in[4];
    const float* la_b      = (const float*)d_in[5];
    const float* mix_w     = (const float*)d_in[6];
    const float* g_w       = (const float*)d_in[7];
    const float* g_b       = (const float*)d_in[8];
    const float* fc_w      = (const float*)d_in[9];
    const float* fc_b      = (const float*)d_in[10];
    const float* fg_w      = (const float*)d_in[11];
    const float* fg_b      = (const float*)d_in[12];
    float* out = (float*)d_out;

    dim3 g1((TQ + K1SPAN - 1) / K1SPAN, NBQ, BQ);  // 118 x 8 x 4
    k1_xp<<<g1, K1B>>>(x, log_gamma, diff_w, diff_b);

    // PDL attribute: k2/k3 may start early; they gate on
    // cudaGridDependencySynchronize() before touching predecessor output.
    cudaLaunchAttribute attr[1];
    attr[0].id = cudaLaunchAttributeProgrammaticStreamSerialization;
    attr[0].val.programmaticStreamSerializationAllowed = 1;

    {
        cudaLaunchConfig_t cfg = {};
        cfg.gridDim  = dim3(NTILE, BQ, 1);         // 118 x 4
        cfg.blockDim = dim3(256, 1, 1);
        cfg.stream   = (cudaStream_t)0;
        cfg.attrs    = attr;
        cfg.numAttrs = 1;
        cudaLaunchKernelEx(&cfg, k2_xgC, la_w, la_b, mix_w, g_w, g_b, fg_w);
    }
    {
        cudaLaunchConfig_t cfg = {};
        cfg.gridDim  = dim3((TQ / 4 + 127) / 128, BQ, 1);  // 118 x 4
        cfg.blockDim = dim3(128, 1, 1);
        cfg.stream   = (cudaStream_t)0;
        cfg.attrs    = attr;
        cfg.numAttrs = 1;
        cudaLaunchKernelEx(&cfg, k3_out, fc_w, fc_b, fg_w, fg_b,
                           out, out + (size_t)BQ * TQ);
    }
}